// round 8
// baseline (speedup 1.0000x reference)
#include <cuda_runtime.h>
#include <cstdint>

// ModConv1x1 via mma.sync.m16n8k8 tf32, round 8.
// Warp tile 64x64 (was 64x32): LDS bytes/FLOP -33%. 128-thread CTAs,
// 2 CTAs/SM. x streamed GMEM->SMEM via cp.async (raw fp32 bits; tf32 MMA
// truncates mantissa in HW). A = style-modulated weight, rna-rounded.

constexpr int CIN   = 512;
constexpr int COUT  = 128;
constexpr int HW    = 4096;
constexpr int NTILE = 128;
constexpr int KCHUNK  = 16;
constexpr int NCHUNKS = CIN / KCHUNK;   // 32
constexpr int THREADS = 128;

constexpr int APAD = 20;    // 16 k + 4 pad words
constexpr int BPAD = 136;   // 128 n + 8 pad words

// dynamic smem layout (floats)
constexpr int SM_STYLE_F = 0;                          // 512
constexpr int SM_A_F     = 512;                        // 2*128*20 = 5120
constexpr int SM_B_F     = 512 + 2 * COUT * APAD;      // 2*16*136 = 4352
constexpr int SM_TOTAL   = (SM_B_F + 2 * KCHUNK * BPAD) * 4;   // 39936 B

__device__ __forceinline__ float f2tf(float f) {
    uint32_t r;
    asm("cvt.rna.tf32.f32 %0, %1;" : "=r"(r) : "f"(f));
    return __uint_as_float(r);
}
__device__ __forceinline__ uint32_t smem_u32(const void* p) {
    uint32_t a;
    asm("{ .reg .u64 t; cvta.to.shared.u64 t, %1; cvt.u32.u64 %0, t; }" : "=r"(a) : "l"(p));
    return a;
}
__device__ __forceinline__ void cp_async16(uint32_t dst, const void* src) {
    asm volatile("cp.async.ca.shared.global [%0], [%1], 16;" :: "r"(dst), "l"(src) : "memory");
}
__device__ __forceinline__ void cp_commit() {
    asm volatile("cp.async.commit_group;" ::: "memory");
}
__device__ __forceinline__ void cp_wait0() {
    asm volatile("cp.async.wait_group 0;" ::: "memory");
}

__global__ __launch_bounds__(THREADS, 2)
void modconv_mma2(const float* __restrict__ x,
                  const float* __restrict__ style,
                  const float* __restrict__ weight,
                  float* __restrict__ out)
{
    extern __shared__ float smem[];
    float* style_s = smem + SM_STYLE_F;
    float* A_s     = smem + SM_A_F;     // [2][128][APAD]
    float* B_s     = smem + SM_B_F;     // [2][16][BPAD]

    const int t  = threadIdx.x;
    const int b  = blockIdx.y;
    const int n0 = blockIdx.x * NTILE;

    // style[b,:] -> smem (128 thr x float4 = 512)
    ((float4*)style_s)[t] = ((const float4*)(style + (size_t)b * CIN))[t];

    const float* xb = x + (size_t)b * CIN * HW + n0;
    const uint32_t bsm = smem_u32(B_s);

    // B (x) cp.async map: thread covers row bk, 4 x 16B groups
    const int bk = t >> 3;          // k row 0..15
    const int bg = t & 7;           // 16B-group base, step 8

    // A staging map: thread t owns weight row o = t, all 16 c of the chunk
    const float* wrow_base = weight + (size_t)t * CIN;

    // ---- prologue: issue B chunk 0, LDG weight 0, stage A0
    {
        #pragma unroll
        for (int j = 0; j < 4; ++j) {
            const int cg = bg + 8 * j;
            cp_async16(bsm + (uint32_t)(bk * BPAD + cg * 4) * 4,
                       xb + (size_t)bk * HW + cg * 4);
        }
        cp_commit();
    }
    float4 wreg[4];
    #pragma unroll
    for (int j = 0; j < 4; ++j)
        wreg[j] = *(const float4*)(wrow_base + 4 * j);
    __syncthreads();   // style ready
    {
        float* Ar = A_s + t * APAD;
        #pragma unroll
        for (int j = 0; j < 4; ++j) {
            float4 av;
            av.x = f2tf(wreg[j].x * style_s[4 * j + 0]);
            av.y = f2tf(wreg[j].y * style_s[4 * j + 1]);
            av.z = f2tf(wreg[j].z * style_s[4 * j + 2]);
            av.w = f2tf(wreg[j].w * style_s[4 * j + 3]);
            *(float4*)(Ar + 4 * j) = av;
        }
    }

    // ---- compute maps: 4 warps = 2(M) x 2(N), warp tile 64 x 64
    const int lane = t & 31, wid = t >> 5;
    const int mB = (wid >> 1) * 64;
    const int nB = (wid & 1) * 64;
    const int gp = lane >> 2;   // 0..7
    const int tg = lane & 3;    // 0..3

    float acc[4][8][4];
    #pragma unroll
    for (int mt = 0; mt < 4; ++mt)
        #pragma unroll
        for (int nt = 0; nt < 8; ++nt)
            #pragma unroll
            for (int i = 0; i < 4; ++i) acc[mt][nt][i] = 0.f;

    #pragma unroll 1
    for (int kc = 0; kc < NCHUNKS; ++kc) {
        const int buf = kc & 1;
        const bool more = (kc + 1 < NCHUNKS);
        const int c0n = (kc + 1) * KCHUNK;

        // all chunk-kc copies (all threads') landed; barrier publishes them
        cp_wait0();
        __syncthreads();

        // issue chunk kc+1 into buf^1 (B via cp.async, weight via LDG)
        if (more) {
            const uint32_t bdst = bsm + (uint32_t)((buf ^ 1) * KCHUNK * BPAD) * 4;
            #pragma unroll
            for (int j = 0; j < 4; ++j) {
                const int cg = bg + 8 * j;
                cp_async16(bdst + (uint32_t)(bk * BPAD + cg * 4) * 4,
                           xb + (size_t)(c0n + bk) * HW + cg * 4);
            }
            cp_commit();
            #pragma unroll
            for (int j = 0; j < 4; ++j)
                wreg[j] = *(const float4*)(wrow_base + c0n + 4 * j);
        }

        // compute chunk kc: 2 k8-steps x (4m x 8n) MMAs
        const float* Ab = A_s + buf * COUT * APAD;
        const float* Bb = B_s + buf * KCHUNK * BPAD;
        #pragma unroll
        for (int ks = 0; ks < 2; ++ks) {
            const int kk = ks * 8;
            uint32_t a[4][4], bf[8][2];
            #pragma unroll
            for (int mt = 0; mt < 4; ++mt) {
                const float* ap = Ab + (size_t)(mB + mt * 16 + gp) * APAD + kk + tg;
                a[mt][0] = __float_as_uint(ap[0]);
                a[mt][1] = __float_as_uint(ap[8 * APAD]);
                a[mt][2] = __float_as_uint(ap[4]);
                a[mt][3] = __float_as_uint(ap[8 * APAD + 4]);
            }
            #pragma unroll
            for (int nt = 0; nt < 8; ++nt) {
                const float* bp = Bb + (size_t)(kk + tg) * BPAD + nB + nt * 8 + gp;
                bf[nt][0] = __float_as_uint(bp[0]);
                bf[nt][1] = __float_as_uint(bp[4 * BPAD]);
            }
            #pragma unroll
            for (int mt = 0; mt < 4; ++mt)
                #pragma unroll
                for (int nt = 0; nt < 8; ++nt) {
                    asm volatile(
                        "mma.sync.aligned.m16n8k8.row.col.f32.tf32.tf32.f32 "
                        "{%0,%1,%2,%3}, {%4,%5,%6,%7}, {%8,%9}, {%0,%1,%2,%3};"
                        : "+f"(acc[mt][nt][0]), "+f"(acc[mt][nt][1]),
                          "+f"(acc[mt][nt][2]), "+f"(acc[mt][nt][3])
                        : "r"(a[mt][0]), "r"(a[mt][1]), "r"(a[mt][2]), "r"(a[mt][3]),
                          "r"(bf[nt][0]), "r"(bf[nt][1]));
                }
        }

        // stage A chunk kc+1 into buf^1 (LDG latency hidden by compute above)
        if (more) {
            float* Ar = A_s + (buf ^ 1) * COUT * APAD + t * APAD;
            #pragma unroll
            for (int j = 0; j < 4; ++j) {
                float4 av;
                av.x = f2tf(wreg[j].x * style_s[c0n + 4 * j + 0]);
                av.y = f2tf(wreg[j].y * style_s[c0n + 4 * j + 1]);
                av.z = f2tf(wreg[j].z * style_s[c0n + 4 * j + 2]);
                av.w = f2tf(wreg[j].w * style_s[c0n + 4 * j + 3]);
                *(float4*)(Ar + 4 * j) = av;
            }
        }
    }

    // ---- epilogue: direct STG.64, rows = o, cols = hw
    float* ob = out + (size_t)b * COUT * HW + n0;
    #pragma unroll
    for (int mt = 0; mt < 4; ++mt) {
        const int o0 = mB + mt * 16 + gp;
        #pragma unroll
        for (int nt = 0; nt < 8; ++nt) {
            const int col = nB + nt * 8 + 2 * tg;
            *(float2*)(ob + (size_t)o0 * HW + col) =
                make_float2(acc[mt][nt][0], acc[mt][nt][1]);
            *(float2*)(ob + (size_t)(o0 + 8) * HW + col) =
                make_float2(acc[mt][nt][2], acc[mt][nt][3]);
        }
    }
}

extern "C" void kernel_launch(void* const* d_in, const int* in_sizes, int n_in,
                              void* d_out, int out_size)
{
    const float* x      = (const float*)d_in[0];  // [16,512,64,64]
    const float* style  = (const float*)d_in[1];  // [16,512]
    const float* weight = (const float*)d_in[2];  // [128,512]
    float* out = (float*)d_out;                   // [16,128,64,64]

    dim3 grid(HW / NTILE, 16);                    // 32 x 16 = 512 CTAs
    modconv_mma2<<<grid, THREADS, SM_TOTAL>>>(x, style, weight, out);
}

// round 9
// speedup vs baseline: 1.0003x; 1.0003x over previous
#include <cuda_runtime.h>
#include <cstdint>

// ModConv1x1 via mma.sync.m16n8k8 tf32, round 8.
// Warp tile 64x64 (was 64x32): LDS bytes/FLOP -33%. 128-thread CTAs,
// 2 CTAs/SM. x streamed GMEM->SMEM via cp.async (raw fp32 bits; tf32 MMA
// truncates mantissa in HW). A = style-modulated weight, rna-rounded.

constexpr int CIN   = 512;
constexpr int COUT  = 128;
constexpr int HW    = 4096;
constexpr int NTILE = 128;
constexpr int KCHUNK  = 16;
constexpr int NCHUNKS = CIN / KCHUNK;   // 32
constexpr int THREADS = 128;

constexpr int APAD = 20;    // 16 k + 4 pad words
constexpr int BPAD = 136;   // 128 n + 8 pad words

// dynamic smem layout (floats)
constexpr int SM_STYLE_F = 0;                          // 512
constexpr int SM_A_F     = 512;                        // 2*128*20 = 5120
constexpr int SM_B_F     = 512 + 2 * COUT * APAD;      // 2*16*136 = 4352
constexpr int SM_TOTAL   = (SM_B_F + 2 * KCHUNK * BPAD) * 4;   // 39936 B

__device__ __forceinline__ float f2tf(float f) {
    uint32_t r;
    asm("cvt.rna.tf32.f32 %0, %1;" : "=r"(r) : "f"(f));
    return __uint_as_float(r);
}
__device__ __forceinline__ uint32_t smem_u32(const void* p) {
    uint32_t a;
    asm("{ .reg .u64 t; cvta.to.shared.u64 t, %1; cvt.u32.u64 %0, t; }" : "=r"(a) : "l"(p));
    return a;
}
__device__ __forceinline__ void cp_async16(uint32_t dst, const void* src) {
    asm volatile("cp.async.ca.shared.global [%0], [%1], 16;" :: "r"(dst), "l"(src) : "memory");
}
__device__ __forceinline__ void cp_commit() {
    asm volatile("cp.async.commit_group;" ::: "memory");
}
__device__ __forceinline__ void cp_wait0() {
    asm volatile("cp.async.wait_group 0;" ::: "memory");
}

__global__ __launch_bounds__(THREADS, 2)
void modconv_mma2(const float* __restrict__ x,
                  const float* __restrict__ style,
                  const float* __restrict__ weight,
                  float* __restrict__ out)
{
    extern __shared__ float smem[];
    float* style_s = smem + SM_STYLE_F;
    float* A_s     = smem + SM_A_F;     // [2][128][APAD]
    float* B_s     = smem + SM_B_F;     // [2][16][BPAD]

    const int t  = threadIdx.x;
    const int b  = blockIdx.y;
    const int n0 = blockIdx.x * NTILE;

    // style[b,:] -> smem (128 thr x float4 = 512)
    ((float4*)style_s)[t] = ((const float4*)(style + (size_t)b * CIN))[t];

    const float* xb = x + (size_t)b * CIN * HW + n0;
    const uint32_t bsm = smem_u32(B_s);

    // B (x) cp.async map: thread covers row bk, 4 x 16B groups
    const int bk = t >> 3;          // k row 0..15
    const int bg = t & 7;           // 16B-group base, step 8

    // A staging map: thread t owns weight row o = t, all 16 c of the chunk
    const float* wrow_base = weight + (size_t)t * CIN;

    // ---- prologue: issue B chunk 0, LDG weight 0, stage A0
    {
        #pragma unroll
        for (int j = 0; j < 4; ++j) {
            const int cg = bg + 8 * j;
            cp_async16(bsm + (uint32_t)(bk * BPAD + cg * 4) * 4,
                       xb + (size_t)bk * HW + cg * 4);
        }
        cp_commit();
    }
    float4 wreg[4];
    #pragma unroll
    for (int j = 0; j < 4; ++j)
        wreg[j] = *(const float4*)(wrow_base + 4 * j);
    __syncthreads();   // style ready
    {
        float* Ar = A_s + t * APAD;
        #pragma unroll
        for (int j = 0; j < 4; ++j) {
            float4 av;
            av.x = f2tf(wreg[j].x * style_s[4 * j + 0]);
            av.y = f2tf(wreg[j].y * style_s[4 * j + 1]);
            av.z = f2tf(wreg[j].z * style_s[4 * j + 2]);
            av.w = f2tf(wreg[j].w * style_s[4 * j + 3]);
            *(float4*)(Ar + 4 * j) = av;
        }
    }

    // ---- compute maps: 4 warps = 2(M) x 2(N), warp tile 64 x 64
    const int lane = t & 31, wid = t >> 5;
    const int mB = (wid >> 1) * 64;
    const int nB = (wid & 1) * 64;
    const int gp = lane >> 2;   // 0..7
    const int tg = lane & 3;    // 0..3

    float acc[4][8][4];
    #pragma unroll
    for (int mt = 0; mt < 4; ++mt)
        #pragma unroll
        for (int nt = 0; nt < 8; ++nt)
            #pragma unroll
            for (int i = 0; i < 4; ++i) acc[mt][nt][i] = 0.f;

    #pragma unroll 1
    for (int kc = 0; kc < NCHUNKS; ++kc) {
        const int buf = kc & 1;
        const bool more = (kc + 1 < NCHUNKS);
        const int c0n = (kc + 1) * KCHUNK;

        // all chunk-kc copies (all threads') landed; barrier publishes them
        cp_wait0();
        __syncthreads();

        // issue chunk kc+1 into buf^1 (B via cp.async, weight via LDG)
        if (more) {
            const uint32_t bdst = bsm + (uint32_t)((buf ^ 1) * KCHUNK * BPAD) * 4;
            #pragma unroll
            for (int j = 0; j < 4; ++j) {
                const int cg = bg + 8 * j;
                cp_async16(bdst + (uint32_t)(bk * BPAD + cg * 4) * 4,
                           xb + (size_t)(c0n + bk) * HW + cg * 4);
            }
            cp_commit();
            #pragma unroll
            for (int j = 0; j < 4; ++j)
                wreg[j] = *(const float4*)(wrow_base + c0n + 4 * j);
        }

        // compute chunk kc: 2 k8-steps x (4m x 8n) MMAs
        const float* Ab = A_s + buf * COUT * APAD;
        const float* Bb = B_s + buf * KCHUNK * BPAD;
        #pragma unroll
        for (int ks = 0; ks < 2; ++ks) {
            const int kk = ks * 8;
            uint32_t a[4][4], bf[8][2];
            #pragma unroll
            for (int mt = 0; mt < 4; ++mt) {
                const float* ap = Ab + (size_t)(mB + mt * 16 + gp) * APAD + kk + tg;
                a[mt][0] = __float_as_uint(ap[0]);
                a[mt][1] = __float_as_uint(ap[8 * APAD]);
                a[mt][2] = __float_as_uint(ap[4]);
                a[mt][3] = __float_as_uint(ap[8 * APAD + 4]);
            }
            #pragma unroll
            for (int nt = 0; nt < 8; ++nt) {
                const float* bp = Bb + (size_t)(kk + tg) * BPAD + nB + nt * 8 + gp;
                bf[nt][0] = __float_as_uint(bp[0]);
                bf[nt][1] = __float_as_uint(bp[4 * BPAD]);
            }
            #pragma unroll
            for (int mt = 0; mt < 4; ++mt)
                #pragma unroll
                for (int nt = 0; nt < 8; ++nt) {
                    asm volatile(
                        "mma.sync.aligned.m16n8k8.row.col.f32.tf32.tf32.f32 "
                        "{%0,%1,%2,%3}, {%4,%5,%6,%7}, {%8,%9}, {%0,%1,%2,%3};"
                        : "+f"(acc[mt][nt][0]), "+f"(acc[mt][nt][1]),
                          "+f"(acc[mt][nt][2]), "+f"(acc[mt][nt][3])
                        : "r"(a[mt][0]), "r"(a[mt][1]), "r"(a[mt][2]), "r"(a[mt][3]),
                          "r"(bf[nt][0]), "r"(bf[nt][1]));
                }
        }

        // stage A chunk kc+1 into buf^1 (LDG latency hidden by compute above)
        if (more) {
            float* Ar = A_s + (buf ^ 1) * COUT * APAD + t * APAD;
            #pragma unroll
            for (int j = 0; j < 4; ++j) {
                float4 av;
                av.x = f2tf(wreg[j].x * style_s[c0n + 4 * j + 0]);
                av.y = f2tf(wreg[j].y * style_s[c0n + 4 * j + 1]);
                av.z = f2tf(wreg[j].z * style_s[c0n + 4 * j + 2]);
                av.w = f2tf(wreg[j].w * style_s[c0n + 4 * j + 3]);
                *(float4*)(Ar + 4 * j) = av;
            }
        }
    }

    // ---- epilogue: direct STG.64, rows = o, cols = hw
    float* ob = out + (size_t)b * COUT * HW + n0;
    #pragma unroll
    for (int mt = 0; mt < 4; ++mt) {
        const int o0 = mB + mt * 16 + gp;
        #pragma unroll
        for (int nt = 0; nt < 8; ++nt) {
            const int col = nB + nt * 8 + 2 * tg;
            *(float2*)(ob + (size_t)o0 * HW + col) =
                make_float2(acc[mt][nt][0], acc[mt][nt][1]);
            *(float2*)(ob + (size_t)(o0 + 8) * HW + col) =
                make_float2(acc[mt][nt][2], acc[mt][nt][3]);
        }
    }
}

extern "C" void kernel_launch(void* const* d_in, const int* in_sizes, int n_in,
                              void* d_out, int out_size)
{
    const float* x      = (const float*)d_in[0];  // [16,512,64,64]
    const float* style  = (const float*)d_in[1];  // [16,512]
    const float* weight = (const float*)d_in[2];  // [128,512]
    float* out = (float*)d_out;                   // [16,128,64,64]

    dim3 grid(HW / NTILE, 16);                    // 32 x 16 = 512 CTAs
    modconv_mma2<<<grid, THREADS, SM_TOTAL>>>(x, style, weight, out);
}

// round 10
// speedup vs baseline: 1.0024x; 1.0020x over previous
#include <cuda_runtime.h>
#include <cstdint>

// ModConv1x1 via mma.sync.m16n8k8 tf32, round 8.
// Warp tile 64x64 (was 64x32): LDS bytes/FLOP -33%. 128-thread CTAs,
// 2 CTAs/SM. x streamed GMEM->SMEM via cp.async (raw fp32 bits; tf32 MMA
// truncates mantissa in HW). A = style-modulated weight, rna-rounded.

constexpr int CIN   = 512;
constexpr int COUT  = 128;
constexpr int HW    = 4096;
constexpr int NTILE = 128;
constexpr int KCHUNK  = 16;
constexpr int NCHUNKS = CIN / KCHUNK;   // 32
constexpr int THREADS = 128;

constexpr int APAD = 20;    // 16 k + 4 pad words
constexpr int BPAD = 136;   // 128 n + 8 pad words

// dynamic smem layout (floats)
constexpr int SM_STYLE_F = 0;                          // 512
constexpr int SM_A_F     = 512;                        // 2*128*20 = 5120
constexpr int SM_B_F     = 512 + 2 * COUT * APAD;      // 2*16*136 = 4352
constexpr int SM_TOTAL   = (SM_B_F + 2 * KCHUNK * BPAD) * 4;   // 39936 B

__device__ __forceinline__ float f2tf(float f) {
    uint32_t r;
    asm("cvt.rna.tf32.f32 %0, %1;" : "=r"(r) : "f"(f));
    return __uint_as_float(r);
}
__device__ __forceinline__ uint32_t smem_u32(const void* p) {
    uint32_t a;
    asm("{ .reg .u64 t; cvta.to.shared.u64 t, %1; cvt.u32.u64 %0, t; }" : "=r"(a) : "l"(p));
    return a;
}
__device__ __forceinline__ void cp_async16(uint32_t dst, const void* src) {
    asm volatile("cp.async.ca.shared.global [%0], [%1], 16;" :: "r"(dst), "l"(src) : "memory");
}
__device__ __forceinline__ void cp_commit() {
    asm volatile("cp.async.commit_group;" ::: "memory");
}
__device__ __forceinline__ void cp_wait0() {
    asm volatile("cp.async.wait_group 0;" ::: "memory");
}

__global__ __launch_bounds__(THREADS, 2)
void modconv_mma2(const float* __restrict__ x,
                  const float* __restrict__ style,
                  const float* __restrict__ weight,
                  float* __restrict__ out)
{
    extern __shared__ float smem[];
    float* style_s = smem + SM_STYLE_F;
    float* A_s     = smem + SM_A_F;     // [2][128][APAD]
    float* B_s     = smem + SM_B_F;     // [2][16][BPAD]

    const int t  = threadIdx.x;
    const int b  = blockIdx.y;
    const int n0 = blockIdx.x * NTILE;

    // style[b,:] -> smem (128 thr x float4 = 512)
    ((float4*)style_s)[t] = ((const float4*)(style + (size_t)b * CIN))[t];

    const float* xb = x + (size_t)b * CIN * HW + n0;
    const uint32_t bsm = smem_u32(B_s);

    // B (x) cp.async map: thread covers row bk, 4 x 16B groups
    const int bk = t >> 3;          // k row 0..15
    const int bg = t & 7;           // 16B-group base, step 8

    // A staging map: thread t owns weight row o = t, all 16 c of the chunk
    const float* wrow_base = weight + (size_t)t * CIN;

    // ---- prologue: issue B chunk 0, LDG weight 0, stage A0
    {
        #pragma unroll
        for (int j = 0; j < 4; ++j) {
            const int cg = bg + 8 * j;
            cp_async16(bsm + (uint32_t)(bk * BPAD + cg * 4) * 4,
                       xb + (size_t)bk * HW + cg * 4);
        }
        cp_commit();
    }
    float4 wreg[4];
    #pragma unroll
    for (int j = 0; j < 4; ++j)
        wreg[j] = *(const float4*)(wrow_base + 4 * j);
    __syncthreads();   // style ready
    {
        float* Ar = A_s + t * APAD;
        #pragma unroll
        for (int j = 0; j < 4; ++j) {
            float4 av;
            av.x = f2tf(wreg[j].x * style_s[4 * j + 0]);
            av.y = f2tf(wreg[j].y * style_s[4 * j + 1]);
            av.z = f2tf(wreg[j].z * style_s[4 * j + 2]);
            av.w = f2tf(wreg[j].w * style_s[4 * j + 3]);
            *(float4*)(Ar + 4 * j) = av;
        }
    }

    // ---- compute maps: 4 warps = 2(M) x 2(N), warp tile 64 x 64
    const int lane = t & 31, wid = t >> 5;
    const int mB = (wid >> 1) * 64;
    const int nB = (wid & 1) * 64;
    const int gp = lane >> 2;   // 0..7
    const int tg = lane & 3;    // 0..3

    float acc[4][8][4];
    #pragma unroll
    for (int mt = 0; mt < 4; ++mt)
        #pragma unroll
        for (int nt = 0; nt < 8; ++nt)
            #pragma unroll
            for (int i = 0; i < 4; ++i) acc[mt][nt][i] = 0.f;

    #pragma unroll 1
    for (int kc = 0; kc < NCHUNKS; ++kc) {
        const int buf = kc & 1;
        const bool more = (kc + 1 < NCHUNKS);
        const int c0n = (kc + 1) * KCHUNK;

        // all chunk-kc copies (all threads') landed; barrier publishes them
        cp_wait0();
        __syncthreads();

        // issue chunk kc+1 into buf^1 (B via cp.async, weight via LDG)
        if (more) {
            const uint32_t bdst = bsm + (uint32_t)((buf ^ 1) * KCHUNK * BPAD) * 4;
            #pragma unroll
            for (int j = 0; j < 4; ++j) {
                const int cg = bg + 8 * j;
                cp_async16(bdst + (uint32_t)(bk * BPAD + cg * 4) * 4,
                           xb + (size_t)(c0n + bk) * HW + cg * 4);
            }
            cp_commit();
            #pragma unroll
            for (int j = 0; j < 4; ++j)
                wreg[j] = *(const float4*)(wrow_base + c0n + 4 * j);
        }

        // compute chunk kc: 2 k8-steps x (4m x 8n) MMAs
        const float* Ab = A_s + buf * COUT * APAD;
        const float* Bb = B_s + buf * KCHUNK * BPAD;
        #pragma unroll
        for (int ks = 0; ks < 2; ++ks) {
            const int kk = ks * 8;
            uint32_t a[4][4], bf[8][2];
            #pragma unroll
            for (int mt = 0; mt < 4; ++mt) {
                const float* ap = Ab + (size_t)(mB + mt * 16 + gp) * APAD + kk + tg;
                a[mt][0] = __float_as_uint(ap[0]);
                a[mt][1] = __float_as_uint(ap[8 * APAD]);
                a[mt][2] = __float_as_uint(ap[4]);
                a[mt][3] = __float_as_uint(ap[8 * APAD + 4]);
            }
            #pragma unroll
            for (int nt = 0; nt < 8; ++nt) {
                const float* bp = Bb + (size_t)(kk + tg) * BPAD + nB + nt * 8 + gp;
                bf[nt][0] = __float_as_uint(bp[0]);
                bf[nt][1] = __float_as_uint(bp[4 * BPAD]);
            }
            #pragma unroll
            for (int mt = 0; mt < 4; ++mt)
                #pragma unroll
                for (int nt = 0; nt < 8; ++nt) {
                    asm volatile(
                        "mma.sync.aligned.m16n8k8.row.col.f32.tf32.tf32.f32 "
                        "{%0,%1,%2,%3}, {%4,%5,%6,%7}, {%8,%9}, {%0,%1,%2,%3};"
                        : "+f"(acc[mt][nt][0]), "+f"(acc[mt][nt][1]),
                          "+f"(acc[mt][nt][2]), "+f"(acc[mt][nt][3])
                        : "r"(a[mt][0]), "r"(a[mt][1]), "r"(a[mt][2]), "r"(a[mt][3]),
                          "r"(bf[nt][0]), "r"(bf[nt][1]));
                }
        }

        // stage A chunk kc+1 into buf^1 (LDG latency hidden by compute above)
        if (more) {
            float* Ar = A_s + (buf ^ 1) * COUT * APAD + t * APAD;
            #pragma unroll
            for (int j = 0; j < 4; ++j) {
                float4 av;
                av.x = f2tf(wreg[j].x * style_s[c0n + 4 * j + 0]);
                av.y = f2tf(wreg[j].y * style_s[c0n + 4 * j + 1]);
                av.z = f2tf(wreg[j].z * style_s[c0n + 4 * j + 2]);
                av.w = f2tf(wreg[j].w * style_s[c0n + 4 * j + 3]);
                *(float4*)(Ar + 4 * j) = av;
            }
        }
    }

    // ---- epilogue: direct STG.64, rows = o, cols = hw
    float* ob = out + (size_t)b * COUT * HW + n0;
    #pragma unroll
    for (int mt = 0; mt < 4; ++mt) {
        const int o0 = mB + mt * 16 + gp;
        #pragma unroll
        for (int nt = 0; nt < 8; ++nt) {
            const int col = nB + nt * 8 + 2 * tg;
            *(float2*)(ob + (size_t)o0 * HW + col) =
                make_float2(acc[mt][nt][0], acc[mt][nt][1]);
            *(float2*)(ob + (size_t)(o0 + 8) * HW + col) =
                make_float2(acc[mt][nt][2], acc[mt][nt][3]);
        }
    }
}

extern "C" void kernel_launch(void* const* d_in, const int* in_sizes, int n_in,
                              void* d_out, int out_size)
{
    const float* x      = (const float*)d_in[0];  // [16,512,64,64]
    const float* style  = (const float*)d_in[1];  // [16,512]
    const float* weight = (const float*)d_in[2];  // [128,512]
    float* out = (float*)d_out;                   // [16,128,64,64]

    dim3 grid(HW / NTILE, 16);                    // 32 x 16 = 512 CTAs
    modconv_mma2<<<grid, THREADS, SM_TOTAL>>>(x, style, weight, out);
}

// round 11
// speedup vs baseline: 1.0061x; 1.0037x over previous
#include <cuda_runtime.h>
#include <cstdint>

// ModConv1x1 via mma.sync.m16n8k8 tf32, round 8.
// Warp tile 64x64 (was 64x32): LDS bytes/FLOP -33%. 128-thread CTAs,
// 2 CTAs/SM. x streamed GMEM->SMEM via cp.async (raw fp32 bits; tf32 MMA
// truncates mantissa in HW). A = style-modulated weight, rna-rounded.

constexpr int CIN   = 512;
constexpr int COUT  = 128;
constexpr int HW    = 4096;
constexpr int NTILE = 128;
constexpr int KCHUNK  = 16;
constexpr int NCHUNKS = CIN / KCHUNK;   // 32
constexpr int THREADS = 128;

constexpr int APAD = 20;    // 16 k + 4 pad words
constexpr int BPAD = 136;   // 128 n + 8 pad words

// dynamic smem layout (floats)
constexpr int SM_STYLE_F = 0;                          // 512
constexpr int SM_A_F     = 512;                        // 2*128*20 = 5120
constexpr int SM_B_F     = 512 + 2 * COUT * APAD;      // 2*16*136 = 4352
constexpr int SM_TOTAL   = (SM_B_F + 2 * KCHUNK * BPAD) * 4;   // 39936 B

__device__ __forceinline__ float f2tf(float f) {
    uint32_t r;
    asm("cvt.rna.tf32.f32 %0, %1;" : "=r"(r) : "f"(f));
    return __uint_as_float(r);
}
__device__ __forceinline__ uint32_t smem_u32(const void* p) {
    uint32_t a;
    asm("{ .reg .u64 t; cvta.to.shared.u64 t, %1; cvt.u32.u64 %0, t; }" : "=r"(a) : "l"(p));
    return a;
}
__device__ __forceinline__ void cp_async16(uint32_t dst, const void* src) {
    asm volatile("cp.async.ca.shared.global [%0], [%1], 16;" :: "r"(dst), "l"(src) : "memory");
}
__device__ __forceinline__ void cp_commit() {
    asm volatile("cp.async.commit_group;" ::: "memory");
}
__device__ __forceinline__ void cp_wait0() {
    asm volatile("cp.async.wait_group 0;" ::: "memory");
}

__global__ __launch_bounds__(THREADS, 2)
void modconv_mma2(const float* __restrict__ x,
                  const float* __restrict__ style,
                  const float* __restrict__ weight,
                  float* __restrict__ out)
{
    extern __shared__ float smem[];
    float* style_s = smem + SM_STYLE_F;
    float* A_s     = smem + SM_A_F;     // [2][128][APAD]
    float* B_s     = smem + SM_B_F;     // [2][16][BPAD]

    const int t  = threadIdx.x;
    const int b  = blockIdx.y;
    const int n0 = blockIdx.x * NTILE;

    // style[b,:] -> smem (128 thr x float4 = 512)
    ((float4*)style_s)[t] = ((const float4*)(style + (size_t)b * CIN))[t];

    const float* xb = x + (size_t)b * CIN * HW + n0;
    const uint32_t bsm = smem_u32(B_s);

    // B (x) cp.async map: thread covers row bk, 4 x 16B groups
    const int bk = t >> 3;          // k row 0..15
    const int bg = t & 7;           // 16B-group base, step 8

    // A staging map: thread t owns weight row o = t, all 16 c of the chunk
    const float* wrow_base = weight + (size_t)t * CIN;

    // ---- prologue: issue B chunk 0, LDG weight 0, stage A0
    {
        #pragma unroll
        for (int j = 0; j < 4; ++j) {
            const int cg = bg + 8 * j;
            cp_async16(bsm + (uint32_t)(bk * BPAD + cg * 4) * 4,
                       xb + (size_t)bk * HW + cg * 4);
        }
        cp_commit();
    }
    float4 wreg[4];
    #pragma unroll
    for (int j = 0; j < 4; ++j)
        wreg[j] = *(const float4*)(wrow_base + 4 * j);
    __syncthreads();   // style ready
    {
        float* Ar = A_s + t * APAD;
        #pragma unroll
        for (int j = 0; j < 4; ++j) {
            float4 av;
            av.x = f2tf(wreg[j].x * style_s[4 * j + 0]);
            av.y = f2tf(wreg[j].y * style_s[4 * j + 1]);
            av.z = f2tf(wreg[j].z * style_s[4 * j + 2]);
            av.w = f2tf(wreg[j].w * style_s[4 * j + 3]);
            *(float4*)(Ar + 4 * j) = av;
        }
    }

    // ---- compute maps: 4 warps = 2(M) x 2(N), warp tile 64 x 64
    const int lane = t & 31, wid = t >> 5;
    const int mB = (wid >> 1) * 64;
    const int nB = (wid & 1) * 64;
    const int gp = lane >> 2;   // 0..7
    const int tg = lane & 3;    // 0..3

    float acc[4][8][4];
    #pragma unroll
    for (int mt = 0; mt < 4; ++mt)
        #pragma unroll
        for (int nt = 0; nt < 8; ++nt)
            #pragma unroll
            for (int i = 0; i < 4; ++i) acc[mt][nt][i] = 0.f;

    #pragma unroll 1
    for (int kc = 0; kc < NCHUNKS; ++kc) {
        const int buf = kc & 1;
        const bool more = (kc + 1 < NCHUNKS);
        const int c0n = (kc + 1) * KCHUNK;

        // all chunk-kc copies (all threads') landed; barrier publishes them
        cp_wait0();
        __syncthreads();

        // issue chunk kc+1 into buf^1 (B via cp.async, weight via LDG)
        if (more) {
            const uint32_t bdst = bsm + (uint32_t)((buf ^ 1) * KCHUNK * BPAD) * 4;
            #pragma unroll
            for (int j = 0; j < 4; ++j) {
                const int cg = bg + 8 * j;
                cp_async16(bdst + (uint32_t)(bk * BPAD + cg * 4) * 4,
                           xb + (size_t)(c0n + bk) * HW + cg * 4);
            }
            cp_commit();
            #pragma unroll
            for (int j = 0; j < 4; ++j)
                wreg[j] = *(const float4*)(wrow_base + c0n + 4 * j);
        }

        // compute chunk kc: 2 k8-steps x (4m x 8n) MMAs
        const float* Ab = A_s + buf * COUT * APAD;
        const float* Bb = B_s + buf * KCHUNK * BPAD;
        #pragma unroll
        for (int ks = 0; ks < 2; ++ks) {
            const int kk = ks * 8;
            uint32_t a[4][4], bf[8][2];
            #pragma unroll
            for (int mt = 0; mt < 4; ++mt) {
                const float* ap = Ab + (size_t)(mB + mt * 16 + gp) * APAD + kk + tg;
                a[mt][0] = __float_as_uint(ap[0]);
                a[mt][1] = __float_as_uint(ap[8 * APAD]);
                a[mt][2] = __float_as_uint(ap[4]);
                a[mt][3] = __float_as_uint(ap[8 * APAD + 4]);
            }
            #pragma unroll
            for (int nt = 0; nt < 8; ++nt) {
                const float* bp = Bb + (size_t)(kk + tg) * BPAD + nB + nt * 8 + gp;
                bf[nt][0] = __float_as_uint(bp[0]);
                bf[nt][1] = __float_as_uint(bp[4 * BPAD]);
            }
            #pragma unroll
            for (int mt = 0; mt < 4; ++mt)
                #pragma unroll
                for (int nt = 0; nt < 8; ++nt) {
                    asm volatile(
                        "mma.sync.aligned.m16n8k8.row.col.f32.tf32.tf32.f32 "
                        "{%0,%1,%2,%3}, {%4,%5,%6,%7}, {%8,%9}, {%0,%1,%2,%3};"
                        : "+f"(acc[mt][nt][0]), "+f"(acc[mt][nt][1]),
                          "+f"(acc[mt][nt][2]), "+f"(acc[mt][nt][3])
                        : "r"(a[mt][0]), "r"(a[mt][1]), "r"(a[mt][2]), "r"(a[mt][3]),
                          "r"(bf[nt][0]), "r"(bf[nt][1]));
                }
        }

        // stage A chunk kc+1 into buf^1 (LDG latency hidden by compute above)
        if (more) {
            float* Ar = A_s + (buf ^ 1) * COUT * APAD + t * APAD;
            #pragma unroll
            for (int j = 0; j < 4; ++j) {
                float4 av;
                av.x = f2tf(wreg[j].x * style_s[c0n + 4 * j + 0]);
                av.y = f2tf(wreg[j].y * style_s[c0n + 4 * j + 1]);
                av.z = f2tf(wreg[j].z * style_s[c0n + 4 * j + 2]);
                av.w = f2tf(wreg[j].w * style_s[c0n + 4 * j + 3]);
                *(float4*)(Ar + 4 * j) = av;
            }
        }
    }

    // ---- epilogue: direct STG.64, rows = o, cols = hw
    float* ob = out + (size_t)b * COUT * HW + n0;
    #pragma unroll
    for (int mt = 0; mt < 4; ++mt) {
        const int o0 = mB + mt * 16 + gp;
        #pragma unroll
        for (int nt = 0; nt < 8; ++nt) {
            const int col = nB + nt * 8 + 2 * tg;
            *(float2*)(ob + (size_t)o0 * HW + col) =
                make_float2(acc[mt][nt][0], acc[mt][nt][1]);
            *(float2*)(ob + (size_t)(o0 + 8) * HW + col) =
                make_float2(acc[mt][nt][2], acc[mt][nt][3]);
        }
    }
}

extern "C" void kernel_launch(void* const* d_in, const int* in_sizes, int n_in,
                              void* d_out, int out_size)
{
    const float* x      = (const float*)d_in[0];  // [16,512,64,64]
    const float* style  = (const float*)d_in[1];  // [16,512]
    const float* weight = (const float*)d_in[2];  // [128,512]
    float* out = (float*)d_out;                   // [16,128,64,64]

    dim3 grid(HW / NTILE, 16);                    // 32 x 16 = 512 CTAs
    modconv_mma2<<<grid, THREADS, SM_TOTAL>>>(x, style, weight, out);
}